// round 6
// baseline (speedup 1.0000x reference)
#include <cuda_runtime.h>
#include <cuda_bf16.h>

// Problem constants
#define C_IN  64
#define C_OUT 64
#define XD 32
#define XH 64
#define XW 64
#define OD 64
#define OH 128
#define OW 128
#define ZD 68
#define ZH 132
#define ZW 132

#define X_CH_STRIDE (XD*XH*XW)      // 131072
#define O_CH_STRIDE (OD*OH*OW)      // 1048576

#define NUM_CONV_BLOCKS 4096        // 32 d' * 64 h' * 2 half-planes
#define NUM_COPY_BLOCKS 4096
#define NUM_BLOCKS (NUM_CONV_BLOCKS + NUM_COPY_BLOCKS)

__global__ __launch_bounds__(256, 8)
void upconv_cropcat_kernel(const float* __restrict__ x,
                           const float* __restrict__ z,
                           const float* __restrict__ W,
                           const float* __restrict__ b,
                           float* __restrict__ out)
{
    // 25 KB total static smem -> 8 CTAs/SM; launch_bounds forces <=32 regs
    __shared__ float xs[64 * 32];     // [c][w'] half-plane tile, 8 KB
    __shared__ float Ws[64 * 65];     // [o][c] padded (conflict-free), 16.25 KB
    __shared__ float bs[64];

    const int bid = blockIdx.x;
    const int tid = threadIdx.x;

    if ((bid & 1) == 0) {
        // ------------------- conv part: half of one (d', h') plane -----------
        const int aid  = bid >> 1;        // 0..4095
        const int dp   = aid >> 7;        // 0..31
        const int hp   = (aid >> 1) & 63; // 0..63
        const int half = aid & 1;         // w' offset 0 or 32

        // Stage W (4096 floats) via float4 loads into padded rows.
        const float4* __restrict__ W4 = (const float4*)W;
        #pragma unroll
        for (int i = tid; i < 1024; i += 256) {
            float4 v = W4[i];
            int o  = i >> 4;
            int c4 = (i & 15) << 2;
            float* dst = &Ws[o * 65 + c4];
            dst[0] = v.x; dst[1] = v.y; dst[2] = v.z; dst[3] = v.w;
        }

        // Stage x tile: 64 channels x 32 w' (contiguous per channel).
        const float* __restrict__ xbase =
            x + dp * (XH * XW) + hp * XW + half * 32;
        float4* xs4 = (float4*)xs;
        #pragma unroll
        for (int i = tid; i < 512; i += 256) {
            int c  = i >> 3;
            int w4 = i & 7;
            xs4[i] = *(const float4*)(xbase + (size_t)c * X_CH_STRIDE + w4 * 4);
        }
        if (tid < 64) bs[tid] = b[tid];
        __syncthreads();

        // Each thread: 2 output channels x 4 small-w values.
        const int wo = tid & 7;    // w-quad: w' = half*32 + wo*4 .. +3
        const int oo = tid >> 3;   // o-pair: o = oo*2, oo*2+1

        float acc[2][4];
        #pragma unroll
        for (int j = 0; j < 2; j++)
            #pragma unroll
            for (int k = 0; k < 4; k++)
                acc[j][k] = 0.0f;

        const float4* __restrict__ xcol = (const float4*)xs + wo;
        #pragma unroll 4
        for (int c = 0; c < 64; c++) {
            float4 xv = xcol[c * 8];
            #pragma unroll
            for (int j = 0; j < 2; j++) {
                float wv = Ws[(oo * 2 + j) * 65 + c];
                acc[j][0] = fmaf(wv, xv.x, acc[j][0]);
                acc[j][1] = fmaf(wv, xv.y, acc[j][1]);
                acc[j][2] = fmaf(wv, xv.z, acc[j][2]);
                acc[j][3] = fmaf(wv, xv.w, acc[j][3]);
            }
        }

        // Epilogue: duplicate each value 2x along w, write 4 output rows
        // (2 d x 2 h). Streaming stores.
        #pragma unroll
        for (int j = 0; j < 2; j++) {
            const int o = oo * 2 + j;
            const float bb = bs[o];
            float4 lo = make_float4(acc[j][0] + bb, acc[j][0] + bb,
                                    acc[j][1] + bb, acc[j][1] + bb);
            float4 hi = make_float4(acc[j][2] + bb, acc[j][2] + bb,
                                    acc[j][3] + bb, acc[j][3] + bb);
            float* obase = out + (size_t)o * O_CH_STRIDE
                               + (size_t)(2 * dp) * (OH * OW)
                               + (2 * hp) * OW + half * 64 + wo * 8;
            #pragma unroll
            for (int dd = 0; dd < 2; dd++) {
                #pragma unroll
                for (int hh = 0; hh < 2; hh++) {
                    float* p = obase + dd * (OH * OW) + hh * OW;
                    __stcs((float4*)p,     lo);
                    __stcs((float4*)(p+4), hi);
                }
            }
        }
    } else {
        // ------------------- crop-copy part -------------------
        // out[64+c, d, h, 0:128] = z[c, d+2, h+2, 2:130]
        // Each warp: 16 h-consecutive rows within one (c, d) plane
        // (r0 multiple of 16, 128 rows per h-plane -> no boundary crossing).
        const int cid  = bid >> 1;
        const int warp = tid >> 5;
        const int lane = tid & 31;
        const int r0 = (cid * 8 + warp) * 16;   // 32768 warps * 16 = 524288 rows

        const int c  = r0 >> 13;        // / (64*128)
        const int rem = r0 & 8191;
        const int d  = rem >> 7;
        const int h0 = rem & 127;

        const float* src =
            z + ((size_t)((c * ZD + d + 2) * ZH + (h0 + 2))) * ZW + 2 + lane * 4;
        float* dst = out + (size_t)(64 + c) * O_CH_STRIDE
                         + (size_t)d * (OH * OW) + h0 * OW + lane * 4;

        #pragma unroll
        for (int jj = 0; jj < 16; jj += 4) {
            float4 v[4];
            #pragma unroll
            for (int i = 0; i < 4; i++) {
                const float* s = src + (jj + i) * ZW;
                float2 a0 = __ldcs((const float2*)s);
                float2 a1 = __ldcs((const float2*)(s + 2));
                v[i] = make_float4(a0.x, a0.y, a1.x, a1.y);
            }
            #pragma unroll
            for (int i = 0; i < 4; i++) {
                __stcs((float4*)(dst + (jj + i) * OW), v[i]);
            }
        }
    }
}

extern "C" void kernel_launch(void* const* d_in, const int* in_sizes, int n_in,
                              void* d_out, int out_size)
{
    const float* x = (const float*)d_in[0];   // (1,64,32,64,64)
    const float* z = (const float*)d_in[1];   // (1,64,68,132,132)
    const float* W = (const float*)d_in[2];   // (64,64)
    const float* b = (const float*)d_in[3];   // (64,)
    float* out = (float*)d_out;               // (1,128,64,128,128)

    upconv_cropcat_kernel<<<NUM_BLOCKS, 256>>>(x, z, W, b, out);
}

// round 7
// speedup vs baseline: 1.1968x; 1.1968x over previous
#include <cuda_runtime.h>
#include <cuda_bf16.h>

// Problem constants
#define C_IN  64
#define C_OUT 64
#define XD 32
#define XH 64
#define XW 64
#define OD 64
#define OH 128
#define OW 128
#define ZD 68
#define ZH 132
#define ZW 132

#define X_CH_STRIDE (XD*XH*XW)      // 131072
#define O_CH_STRIDE (OD*OH*OW)      // 1048576

#define NUM_CONV_BLOCKS 4096        // 32 d' * 64 h' * 2 half-planes
#define NUM_COPY_BLOCKS 4096
#define NUM_BLOCKS (NUM_CONV_BLOCKS + NUM_COPY_BLOCKS)

__global__ __launch_bounds__(256)
void upconv_cropcat_kernel(const float* __restrict__ x,
                           const float* __restrict__ z,
                           const float* __restrict__ W,
                           const float* __restrict__ b,
                           float* __restrict__ out)
{
    __shared__ float xs[64 * 32];     // [c][w'] half-plane tile, 8 KB
    __shared__ float Ws[64 * 65];     // [o][c] padded (conflict-free), 16.25 KB
    __shared__ float bs[64];

    const int bid = blockIdx.x;
    const int tid = threadIdx.x;

    if ((bid & 1) == 0) {
        // ------------------- conv part: half of one (d', h') plane -----------
        const int aid  = bid >> 1;        // 0..4095
        const int dp   = aid >> 7;        // 0..31
        const int hp   = (aid >> 1) & 63; // 0..63
        const int half = aid & 1;         // w' offset 0 or 32

        // Stage W (4096 floats) via float4 loads into padded rows.
        const float4* __restrict__ W4 = (const float4*)W;
        #pragma unroll
        for (int i = tid; i < 1024; i += 256) {
            float4 v = W4[i];
            int o  = i >> 4;
            int c4 = (i & 15) << 2;
            float* dst = &Ws[o * 65 + c4];
            dst[0] = v.x; dst[1] = v.y; dst[2] = v.z; dst[3] = v.w;
        }

        // Stage x tile: 64 channels x 32 w' (contiguous per channel).
        const float* __restrict__ xbase =
            x + dp * (XH * XW) + hp * XW + half * 32;
        float4* xs4 = (float4*)xs;
        #pragma unroll
        for (int i = tid; i < 512; i += 256) {
            int c  = i >> 3;
            int w4 = i & 7;
            xs4[i] = *(const float4*)(xbase + (size_t)c * X_CH_STRIDE + w4 * 4);
        }
        if (tid < 64) bs[tid] = b[tid];
        __syncthreads();

        // Each thread: 2 output channels x 4 small-w values.
        const int wo = tid & 7;    // w-quad: w' = half*32 + wo*4 .. +3
        const int oo = tid >> 3;   // o-pair: o = oo*2, oo*2+1

        float acc[2][4];
        #pragma unroll
        for (int j = 0; j < 2; j++)
            #pragma unroll
            for (int k = 0; k < 4; k++)
                acc[j][k] = 0.0f;

        const float4* __restrict__ xcol = (const float4*)xs + wo;
        #pragma unroll 8
        for (int c = 0; c < 64; c++) {
            float4 xv = xcol[c * 8];
            #pragma unroll
            for (int j = 0; j < 2; j++) {
                float wv = Ws[(oo * 2 + j) * 65 + c];
                acc[j][0] = fmaf(wv, xv.x, acc[j][0]);
                acc[j][1] = fmaf(wv, xv.y, acc[j][1]);
                acc[j][2] = fmaf(wv, xv.z, acc[j][2]);
                acc[j][3] = fmaf(wv, xv.w, acc[j][3]);
            }
        }

        // Epilogue: duplicate each value 2x along w, write 4 output rows
        // (2 d x 2 h). Streaming stores.
        #pragma unroll
        for (int j = 0; j < 2; j++) {
            const int o = oo * 2 + j;
            const float bb = bs[o];
            float4 lo = make_float4(acc[j][0] + bb, acc[j][0] + bb,
                                    acc[j][1] + bb, acc[j][1] + bb);
            float4 hi = make_float4(acc[j][2] + bb, acc[j][2] + bb,
                                    acc[j][3] + bb, acc[j][3] + bb);
            float* obase = out + (size_t)o * O_CH_STRIDE
                               + (size_t)(2 * dp) * (OH * OW)
                               + (2 * hp) * OW + half * 64 + wo * 8;
            #pragma unroll
            for (int dd = 0; dd < 2; dd++) {
                #pragma unroll
                for (int hh = 0; hh < 2; hh++) {
                    float* p = obase + dd * (OH * OW) + hh * OW;
                    __stcs((float4*)p,     lo);
                    __stcs((float4*)(p+4), hi);
                }
            }
        }
    } else {
        // ------------------- crop-copy part -------------------
        // out[64+c, d, h, 0:128] = z[c, d+2, h+2, 2:130]
        // Each warp: 16 h-consecutive rows within one (c, d) plane
        // (r0 multiple of 16, 128 rows per h-plane -> no boundary crossing).
        // Batch 8 rows of loads (16 x LDG.64 in flight) before storing:
        // per-warp in-flight bytes drive DRAM utilization (R5 lesson).
        const int cid  = bid >> 1;
        const int warp = tid >> 5;
        const int lane = tid & 31;
        const int r0 = (cid * 8 + warp) * 16;   // 32768 warps * 16 = 524288 rows

        const int c   = r0 >> 13;        // / (64*128)
        const int rem = r0 & 8191;
        const int d   = rem >> 7;
        const int h0  = rem & 127;

        const float* src =
            z + ((size_t)((c * ZD + d + 2) * ZH + (h0 + 2))) * ZW + 2 + lane * 4;
        float* dst = out + (size_t)(64 + c) * O_CH_STRIDE
                         + (size_t)d * (OH * OW) + h0 * OW + lane * 4;

        #pragma unroll
        for (int jj = 0; jj < 16; jj += 8) {
            float2 a[8], bb2[8];
            #pragma unroll
            for (int i = 0; i < 8; i++) {
                const float* s = src + (jj + i) * ZW;
                a[i]   = __ldcs((const float2*)s);
                bb2[i] = __ldcs((const float2*)(s + 2));
            }
            #pragma unroll
            for (int i = 0; i < 8; i++) {
                __stcs((float4*)(dst + (jj + i) * OW),
                       make_float4(a[i].x, a[i].y, bb2[i].x, bb2[i].y));
            }
        }
    }
}

extern "C" void kernel_launch(void* const* d_in, const int* in_sizes, int n_in,
                              void* d_out, int out_size)
{
    const float* x = (const float*)d_in[0];   // (1,64,32,64,64)
    const float* z = (const float*)d_in[1];   // (1,64,68,132,132)
    const float* W = (const float*)d_in[2];   // (64,64)
    const float* b = (const float*)d_in[3];   // (64,)
    float* out = (float*)d_out;               // (1,128,64,128,128)

    upconv_cropcat_kernel<<<NUM_BLOCKS, 256>>>(x, z, W, b, out);
}